// round 4
// baseline (speedup 1.0000x reference)
#include <cuda_runtime.h>
#include <math.h>

// Problem constants
#define T_TOK 16384          // B*N tokens
#define D_DIM 768
#define HID_DIM 3072
#define NHEAD 12
#define HD 64
#define QKV_N 2304

// Scratch (device globals: allocation-free per harness rules)
__device__ float g_ln  [(size_t)T_TOK * D_DIM];    //  48 MB (ln1 out, reused for ln2 out)
__device__ float g_qkv [(size_t)T_TOK * QKV_N];    // 144 MB
__device__ float g_attn[(size_t)T_TOK * D_DIM];    //  48 MB
__device__ float g_hid [(size_t)T_TOK * HID_DIM];  // 192 MB

// ---------------------------------------------------------------------------
// LayerNorm: one block per token row of 768 floats. 256 threads, 3 elems each.
// ---------------------------------------------------------------------------
__global__ __launch_bounds__(256) void ln_kernel(
    const float* __restrict__ x, const float* __restrict__ gam,
    const float* __restrict__ bet, float* __restrict__ out)
{
    const int row = blockIdx.x;
    const int tid = threadIdx.x;
    const float* xr = x + (size_t)row * D_DIM;
    float v0 = xr[tid], v1 = xr[tid + 256], v2 = xr[tid + 512];
    float s = v0 + v1 + v2;
    float q = v0 * v0 + v1 * v1 + v2 * v2;

    __shared__ float sred[8], qred[8];
#pragma unroll
    for (int o = 16; o > 0; o >>= 1) {
        s += __shfl_xor_sync(0xffffffffu, s, o);
        q += __shfl_xor_sync(0xffffffffu, q, o);
    }
    if ((tid & 31) == 0) { sred[tid >> 5] = s; qred[tid >> 5] = q; }
    __syncthreads();
    s = 0.f; q = 0.f;
#pragma unroll
    for (int i = 0; i < 8; i++) { s += sred[i]; q += qred[i]; }
    const float mean = s * (1.0f / 768.0f);
    const float var  = q * (1.0f / 768.0f) - mean * mean;
    const float rstd = rsqrtf(var + 1e-6f);

    float* orow = out + (size_t)row * D_DIM;
    orow[tid]       = (v0 - mean) * rstd * gam[tid]       + bet[tid];
    orow[tid + 256] = (v1 - mean) * rstd * gam[tid + 256] + bet[tid + 256];
    orow[tid + 512] = (v2 - mean) * rstd * gam[tid + 512] + bet[tid + 512];
}

// ---------------------------------------------------------------------------
// SGEMM (NT): C[M,N] = A[M,K] * B[N,K]^T, optional bias / GELU / residual.
// 128x128 block tile, BK=16, 256 threads, 8x8 per thread, reg prefetch.
// EPI: 0 = plain, 2 = bias + exact GELU, 3 = bias + residual add
// ---------------------------------------------------------------------------
template <int EPI>
__global__ __launch_bounds__(256, 2) void gemm_nt_kernel(
    const float* __restrict__ A, const float* __restrict__ B,
    const float* __restrict__ bias, const float* __restrict__ resid,
    float* __restrict__ C, int M, int N, int K)
{
    constexpr int BM = 128, BN = 128, BK = 16;
    __shared__ float As[BK][BM + 4];
    __shared__ float Bs[BK][BN + 4];

    const int m0 = blockIdx.y * BM;
    const int n0 = blockIdx.x * BN;
    const int tid = threadIdx.x;
    const int tn = tid & 15, tm = tid >> 4;

    // Load mapping: 2 threads per row, each carries 2 float4 (k-vecs lv, lv+2)
    const int lrow = tid >> 1;
    const int lv   = tid & 1;
    const float* Aptr = A + (size_t)(m0 + lrow) * K;
    const float* Bptr = B + (size_t)(n0 + lrow) * K;

    float4 a0, a1, b0, b1;
    int k0 = 0;
    a0 = *(const float4*)(Aptr + k0 + lv * 4);
    a1 = *(const float4*)(Aptr + k0 + lv * 4 + 8);
    b0 = *(const float4*)(Bptr + k0 + lv * 4);
    b1 = *(const float4*)(Bptr + k0 + lv * 4 + 8);

    float acc[8][8];
#pragma unroll
    for (int i = 0; i < 8; i++)
#pragma unroll
        for (int j = 0; j < 8; j++) acc[i][j] = 0.f;

    const int ntiles = K / BK;
    for (int t = 0; t < ntiles; t++) {
        __syncthreads();
#pragma unroll
        for (int j = 0; j < 4; j++) {
            As[lv * 4 + j][lrow]     = ((const float*)&a0)[j];
            As[lv * 4 + 8 + j][lrow] = ((const float*)&a1)[j];
            Bs[lv * 4 + j][lrow]     = ((const float*)&b0)[j];
            Bs[lv * 4 + 8 + j][lrow] = ((const float*)&b1)[j];
        }
        __syncthreads();
        if (t + 1 < ntiles) {
            k0 = (t + 1) * BK;
            a0 = *(const float4*)(Aptr + k0 + lv * 4);
            a1 = *(const float4*)(Aptr + k0 + lv * 4 + 8);
            b0 = *(const float4*)(Bptr + k0 + lv * 4);
            b1 = *(const float4*)(Bptr + k0 + lv * 4 + 8);
        }
#pragma unroll
        for (int k = 0; k < BK; k++) {
            float ar[8], br[8];
            *(float4*)(ar)     = *(const float4*)&As[k][tm * 8];
            *(float4*)(ar + 4) = *(const float4*)&As[k][tm * 8 + 4];
            *(float4*)(br)     = *(const float4*)&Bs[k][tn * 8];
            *(float4*)(br + 4) = *(const float4*)&Bs[k][tn * 8 + 4];
#pragma unroll
            for (int i = 0; i < 8; i++)
#pragma unroll
                for (int j = 0; j < 8; j++)
                    acc[i][j] += ar[i] * br[j];
        }
    }

#pragma unroll
    for (int i = 0; i < 8; i++) {
        const int m = m0 + tm * 8 + i;
        float* crow = C + (size_t)m * N + n0 + tn * 8;
        const float* rrow = (EPI == 3) ? (resid + (size_t)m * N + n0 + tn * 8) : nullptr;
#pragma unroll
        for (int j = 0; j < 8; j++) {
            float v = acc[i][j];
            if (EPI >= 2) v += bias[n0 + tn * 8 + j];
            if (EPI == 2) v = 0.5f * v * (1.0f + erff(v * 0.70710678118654752f));
            if (EPI == 3) v += rrow[j];
            crow[j] = v;
        }
    }
}

// ---------------------------------------------------------------------------
// Flash attention: grid (N/64, B*H). 64 query rows per block, 256 threads,
// 4x4 register tiles, online softmax over 16 key tiles of 64.
// qkv layout: [t, 3, H, HD] packed as 2304 floats per token.
// ---------------------------------------------------------------------------
__global__ __launch_bounds__(256, 2) void attn_kernel(
    const float* __restrict__ qkv, float* __restrict__ out)
{
    __shared__ float QT[64][64];   // Q transposed: [d][r]
    __shared__ float KP[64][64];   // K transposed [d][c], then reused as P [r][c]
    __shared__ float Vs[64][64];   // V natural:   [j][d]

    const int tid = threadIdx.x;
    const int tn = tid & 15, tm = tid >> 4;
    const int bh = blockIdx.y;
    const int b = bh / NHEAD, h = bh - b * NHEAD;
    const int q0 = blockIdx.x * 64;

    const float* Qg = qkv + (size_t)b * 1024 * QKV_N + h * HD;
    const float* Kg = Qg + D_DIM;
    const float* Vg = Qg + 2 * D_DIM;

    // Load Q tile (transposed into smem)
    {
        const int r = tid >> 2;
        const float* src = Qg + (size_t)(q0 + r) * QKV_N;
#pragma unroll
        for (int i = 0; i < 4; i++) {
            const int f = (tid & 3) + i * 4;
            float4 v = *(const float4*)(src + f * 4);
            QT[f * 4 + 0][r] = v.x; QT[f * 4 + 1][r] = v.y;
            QT[f * 4 + 2][r] = v.z; QT[f * 4 + 3][r] = v.w;
        }
    }

    float m_run[4], l_run[4], acc[4][4];
#pragma unroll
    for (int i = 0; i < 4; i++) {
        m_run[i] = -1e30f; l_run[i] = 0.f;
#pragma unroll
        for (int j = 0; j < 4; j++) acc[i][j] = 0.f;
    }

    for (int kt = 0; kt < 16; kt++) {
        __syncthreads();   // previous-iteration P/V consumers done
        {
            const int r = tid >> 2;
            const float* ks  = Kg + (size_t)(kt * 64 + r) * QKV_N;
            const float* vsp = Vg + (size_t)(kt * 64 + r) * QKV_N;
#pragma unroll
            for (int i = 0; i < 4; i++) {
                const int f = (tid & 3) + i * 4;
                float4 kv = *(const float4*)(ks + f * 4);
                KP[f * 4 + 0][r] = kv.x; KP[f * 4 + 1][r] = kv.y;
                KP[f * 4 + 2][r] = kv.z; KP[f * 4 + 3][r] = kv.w;
                float4 vv = *(const float4*)(vsp + f * 4);
                *(float4*)&Vs[r][f * 4] = vv;
            }
        }
        __syncthreads();

        // S = Q K^T (per-thread 4x4 over 64-d inner product)
        float s[4][4];
#pragma unroll
        for (int i = 0; i < 4; i++)
#pragma unroll
            for (int j = 0; j < 4; j++) s[i][j] = 0.f;
#pragma unroll
        for (int d = 0; d < 64; d++) {
            float qr[4], kr[4];
            *(float4*)qr = *(const float4*)&QT[d][tm * 4];
            *(float4*)kr = *(const float4*)&KP[d][tn * 4];
#pragma unroll
            for (int i = 0; i < 4; i++)
#pragma unroll
                for (int j = 0; j < 4; j++)
                    s[i][j] += qr[i] * kr[j];
        }
#pragma unroll
        for (int i = 0; i < 4; i++)
#pragma unroll
            for (int j = 0; j < 4; j++) s[i][j] *= 0.125f;   // HD^-0.5

        // Online softmax (row groups = 16 contiguous lanes within a half-warp)
        float p[4][4];
#pragma unroll
        for (int i = 0; i < 4; i++) {
            float mt = fmaxf(fmaxf(s[i][0], s[i][1]), fmaxf(s[i][2], s[i][3]));
#pragma unroll
            for (int o = 8; o > 0; o >>= 1)
                mt = fmaxf(mt, __shfl_xor_sync(0xffffffffu, mt, o));
            const float mnew = fmaxf(m_run[i], mt);
            const float corr = exp2f((m_run[i] - mnew) * 1.4426950408889634f);
            float rs = 0.f;
#pragma unroll
            for (int j = 0; j < 4; j++) {
                p[i][j] = exp2f((s[i][j] - mnew) * 1.4426950408889634f);
                rs += p[i][j];
            }
#pragma unroll
            for (int o = 8; o > 0; o >>= 1)
                rs += __shfl_xor_sync(0xffffffffu, rs, o);
            l_run[i] = l_run[i] * corr + rs;
            m_run[i] = mnew;
#pragma unroll
            for (int j = 0; j < 4; j++) acc[i][j] *= corr;
        }

        __syncthreads();   // all K-reads of KP done; reuse as P
#pragma unroll
        for (int i = 0; i < 4; i++)
            *(float4*)&KP[tm * 4 + i][tn * 4] = *(const float4*)&p[i][0];
        __syncthreads();

        // acc += P * V
#pragma unroll
        for (int j4 = 0; j4 < 16; j4++) {
            float pr[4][4];
#pragma unroll
            for (int i = 0; i < 4; i++)
                *(float4*)&pr[i][0] = *(const float4*)&KP[tm * 4 + i][j4 * 4];
#pragma unroll
            for (int jj = 0; jj < 4; jj++) {
                float vr[4];
                *(float4*)vr = *(const float4*)&Vs[j4 * 4 + jj][tn * 4];
#pragma unroll
                for (int i = 0; i < 4; i++)
#pragma unroll
                    for (int dc = 0; dc < 4; dc++)
                        acc[i][dc] += pr[i][jj] * vr[dc];
            }
        }
    }

    // Write normalized output, transposed back to [t, h*HD + d]
#pragma unroll
    for (int i = 0; i < 4; i++) {
        const float inv = 1.0f / l_run[i];
        const int t = b * 1024 + q0 + tm * 4 + i;
        float4 o4;
        o4.x = acc[i][0] * inv; o4.y = acc[i][1] * inv;
        o4.z = acc[i][2] * inv; o4.w = acc[i][3] * inv;
        *(float4*)(out + (size_t)t * D_DIM + h * HD + tn * 4) = o4;
    }
}

// ---------------------------------------------------------------------------
// Launch
// ---------------------------------------------------------------------------
extern "C" void kernel_launch(void* const* d_in, const int* in_sizes, int n_in,
                              void* d_out, int out_size)
{
    const float* x      = (const float*)d_in[0];
    const float* qkv_w  = (const float*)d_in[1];
    const float* proj_w = (const float*)d_in[2];
    const float* proj_b = (const float*)d_in[3];
    const float* fc1_w  = (const float*)d_in[4];
    const float* fc1_b  = (const float*)d_in[5];
    const float* fc2_w  = (const float*)d_in[6];
    const float* fc2_b  = (const float*)d_in[7];
    const float* n1g    = (const float*)d_in[8];
    const float* n1b    = (const float*)d_in[9];
    const float* n2g    = (const float*)d_in[10];
    const float* n2b    = (const float*)d_in[11];
    float* out = (float*)d_out;

    void *p_ln, *p_qkv, *p_attn, *p_hid;
    cudaGetSymbolAddress(&p_ln,   g_ln);
    cudaGetSymbolAddress(&p_qkv,  g_qkv);
    cudaGetSymbolAddress(&p_attn, g_attn);
    cudaGetSymbolAddress(&p_hid,  g_hid);
    float* ln   = (float*)p_ln;
    float* qkv  = (float*)p_qkv;
    float* attn = (float*)p_attn;
    float* hid  = (float*)p_hid;

    // 1) LN1
    ln_kernel<<<T_TOK, 256>>>(x, n1g, n1b, ln);
    // 2) QKV = ln1 @ qkv_w^T           [16384, 2304]
    gemm_nt_kernel<0><<<dim3(QKV_N / 128, T_TOK / 128), 256>>>(
        ln, qkv_w, nullptr, nullptr, qkv, T_TOK, QKV_N, D_DIM);
    // 3) attention -> attn [16384, 768]
    attn_kernel<<<dim3(1024 / 64, 16 * NHEAD), 256>>>(qkv, attn);
    // 4) x1 = x + attn @ proj_w^T + proj_b   -> d_out
    gemm_nt_kernel<3><<<dim3(D_DIM / 128, T_TOK / 128), 256>>>(
        attn, proj_w, proj_b, x, out, T_TOK, D_DIM, D_DIM);
    // 5) LN2(x1) -> ln
    ln_kernel<<<T_TOK, 256>>>(out, n2g, n2b, ln);
    // 6) h = gelu(ln2 @ fc1_w^T + fc1_b)   [16384, 3072]
    gemm_nt_kernel<2><<<dim3(HID_DIM / 128, T_TOK / 128), 256>>>(
        ln, fc1_w, fc1_b, nullptr, hid, T_TOK, HID_DIM, D_DIM);
    // 7) out = x1 + h @ fc2_w^T + fc2_b  (in-place residual on d_out)
    gemm_nt_kernel<3><<<dim3(D_DIM / 128, T_TOK / 128), 256>>>(
        hid, fc2_w, fc2_b, out, out, T_TOK, D_DIM, HID_DIM);
}

// round 6
// speedup vs baseline: 1.5167x; 1.5167x over previous
#include <cuda_runtime.h>
#include <cuda_bf16.h>
#include <math.h>
#include <stdint.h>

// ---------------------------------------------------------------------------
// Problem constants
// ---------------------------------------------------------------------------
#define T_TOK 16384          // B*N tokens
#define D_DIM 768
#define HID_DIM 3072
#define NHEAD 12
#define QKV_N 2304
#define K3_D 2304            // 3*768   (hi|lo|hi packed K)
#define K3_H 9216            // 3*3072

// ---------------------------------------------------------------------------
// Scratch (device globals; allocation-free per harness rules)
// ---------------------------------------------------------------------------
__device__ __align__(256) __nv_bfloat16 g_a3  [(size_t)T_TOK * K3_D];   //  72 MB packed activations
__device__ __align__(256) float         g_qkv [(size_t)T_TOK * QKV_N];  // 144 MB
__device__ __align__(256) __nv_bfloat16 g_h3  [(size_t)T_TOK * K3_H];   // 288 MB packed gelu(fc1)
__device__ __align__(256) __nv_bfloat16 g_wqkv3 [(size_t)QKV_N  * K3_D];
__device__ __align__(256) __nv_bfloat16 g_wproj3[(size_t)D_DIM  * K3_D];
__device__ __align__(256) __nv_bfloat16 g_wfc13 [(size_t)HID_DIM* K3_D];
__device__ __align__(256) __nv_bfloat16 g_wfc23 [(size_t)D_DIM  * K3_H];

// ---------------------------------------------------------------------------
// PTX helpers (portable: cp.async / ldmatrix / mma.sync — no 'a'-target ops)
// ---------------------------------------------------------------------------
__device__ __forceinline__ uint32_t smem_u32(const void* p) {
    uint32_t a;
    asm("{ .reg .u64 t; cvta.to.shared.u64 t, %1; cvt.u32.u64 %0, t; }" : "=r"(a) : "l"(p));
    return a;
}

__device__ __forceinline__ void cp16(uint32_t saddr, const void* gaddr) {
    asm volatile("cp.async.cg.shared.global [%0], [%1], 16;" :: "r"(saddr), "l"(gaddr));
}
#define CP_COMMIT() asm volatile("cp.async.commit_group;" ::: "memory")
#define CP_WAIT1()  asm volatile("cp.async.wait_group 1;" ::: "memory")
#define CP_WAIT0()  asm volatile("cp.async.wait_group 0;" ::: "memory")

__device__ __forceinline__ void ldsm4(uint32_t* r, uint32_t addr) {
    asm volatile("ldmatrix.sync.aligned.m8n8.x4.shared.b16 {%0,%1,%2,%3}, [%4];"
                 : "=r"(r[0]), "=r"(r[1]), "=r"(r[2]), "=r"(r[3]) : "r"(addr));
}

__device__ __forceinline__ void mma16816(float* c, const uint32_t* a,
                                         uint32_t b0, uint32_t b1) {
    asm volatile(
        "mma.sync.aligned.m16n8k16.row.col.f32.bf16.bf16.f32 "
        "{%0,%1,%2,%3}, {%4,%5,%6,%7}, {%8,%9}, {%0,%1,%2,%3};"
        : "+f"(c[0]), "+f"(c[1]), "+f"(c[2]), "+f"(c[3])
        : "r"(a[0]), "r"(a[1]), "r"(a[2]), "r"(a[3]), "r"(b0), "r"(b1));
}

__device__ __forceinline__ void split2(float x, __nv_bfloat16& hi, __nv_bfloat16& lo) {
    hi = __float2bfloat16(x);
    lo = __float2bfloat16(x - __bfloat162float(hi));
}

// ---------------------------------------------------------------------------
// Weight pack: W[N,K] fp32 -> W3[N,3K] bf16 as [hi | hi | lo]
// ---------------------------------------------------------------------------
__global__ __launch_bounds__(256) void pack_w_kernel(
    const float* __restrict__ W, __nv_bfloat16* __restrict__ W3, int NK, int K)
{
    int idx = blockIdx.x * 256 + threadIdx.x;
    if (idx >= NK) return;
    int n = idx / K, k = idx - n * K;
    __nv_bfloat16 hi, lo;
    split2(W[idx], hi, lo);
    size_t base = (size_t)n * 3 * K + k;
    W3[base] = hi; W3[base + K] = hi; W3[base + 2 * K] = lo;
}

// ---------------------------------------------------------------------------
// Fused LayerNorm + activation pack: out3[t, 3*768] = [hi | lo | hi]
// ---------------------------------------------------------------------------
__global__ __launch_bounds__(256) void ln_pack_kernel(
    const float* __restrict__ x, const float* __restrict__ gam,
    const float* __restrict__ bet, __nv_bfloat16* __restrict__ out3)
{
    const int row = blockIdx.x;
    const int tid = threadIdx.x;
    const float* xr = x + (size_t)row * D_DIM;
    float v0 = xr[tid], v1 = xr[tid + 256], v2 = xr[tid + 512];
    float s = v0 + v1 + v2;
    float q = v0 * v0 + v1 * v1 + v2 * v2;

    __shared__ float sred[8], qred[8];
#pragma unroll
    for (int o = 16; o > 0; o >>= 1) {
        s += __shfl_xor_sync(0xffffffffu, s, o);
        q += __shfl_xor_sync(0xffffffffu, q, o);
    }
    if ((tid & 31) == 0) { sred[tid >> 5] = s; qred[tid >> 5] = q; }
    __syncthreads();
    s = 0.f; q = 0.f;
#pragma unroll
    for (int i = 0; i < 8; i++) { s += sred[i]; q += qred[i]; }
    const float mean = s * (1.0f / 768.0f);
    const float var  = q * (1.0f / 768.0f) - mean * mean;
    const float rstd = rsqrtf(var + 1e-6f);

    __nv_bfloat16* orow = out3 + (size_t)row * K3_D;
#pragma unroll
    for (int e = 0; e < 3; e++) {
        const int c = tid + e * 256;
        const float v = (e == 0 ? v0 : (e == 1 ? v1 : v2));
        const float y = (v - mean) * rstd * gam[c] + bet[c];
        __nv_bfloat16 hi, lo;
        split2(y, hi, lo);
        orow[c] = hi; orow[c + D_DIM] = lo; orow[c + 2 * D_DIM] = hi;
    }
}

// ---------------------------------------------------------------------------
// HMMA GEMM (NT): C[M,Nf] = A3[M,K3] * B3[Nf,K3]^T  (bf16 in, fp32 accum)
// CTA 128x128, BK=32, 8 warps as 4(m)x2(n), warp tile 32x64,
// double-buffered cp.async smem (80B row stride, conflict-free ldmatrix).
// EPI: 0 = plain fp32; 2 = bias + exact GELU -> packed bf16 [hi|lo|hi];
//      3 = bias + residual -> fp32
// ---------------------------------------------------------------------------
#define SM_STRIDE 40              // elements per smem row (80 bytes)
#define SM_BUF    (128 * SM_STRIDE)

template <int EPI>
__global__ __launch_bounds__(256) void hgemm_kernel(
    const __nv_bfloat16* __restrict__ A3, const __nv_bfloat16* __restrict__ B3,
    const float* __restrict__ bias, const float* __restrict__ resid,
    float* __restrict__ Cf, __nv_bfloat16* __restrict__ Cp,
    int K3, int ldN)
{
    __shared__ __align__(128) __nv_bfloat16 As[2][SM_BUF];
    __shared__ __align__(128) __nv_bfloat16 Bs[2][SM_BUF];

    const int tid  = threadIdx.x;
    const int wid  = tid >> 5;
    const int lane = tid & 31;
    const int wm   = wid >> 1;          // 0..3
    const int wn   = wid & 1;           // 0..1

    const int m0 = blockIdx.y * 128;
    const int n0 = blockIdx.x * 128;

    // Global->smem mapping: 2 threads per row, 32B (16 elems) each
    const int grow = tid >> 1;
    const int ghalf = tid & 1;
    const __nv_bfloat16* ga = A3 + (size_t)(m0 + grow) * K3 + ghalf * 16;
    const __nv_bfloat16* gb = B3 + (size_t)(n0 + grow) * K3 + ghalf * 16;

    const uint32_t as_base = smem_u32(As);
    const uint32_t bs_base = smem_u32(Bs);
    const uint32_t st_off  = grow * 80 + ghalf * 32;

    // ldmatrix base addresses for this warp/lane
    const uint32_t lrow = lane & 15;
    const uint32_t lcol = (lane >> 4) * 16;   // bytes (8 bf16)
    const uint32_t a_ld = as_base + (wm * 32 + lrow) * 80 + lcol;
    const uint32_t b_ld = bs_base + (wn * 64 + lrow) * 80 + lcol;

    float acc[2][8][4];
#pragma unroll
    for (int i = 0; i < 2; i++)
#pragma unroll
        for (int j = 0; j < 8; j++)
#pragma unroll
            for (int v = 0; v < 4; v++) acc[i][j][v] = 0.f;

    const int Tn = K3 / 32;

    // Preload tile 0 into buffer 0
    {
        uint32_t sa = as_base + st_off, sb = bs_base + st_off;
        cp16(sa, ga);      cp16(sa + 16, ga + 8);
        cp16(sb, gb);      cp16(sb + 16, gb + 8);
    }
    CP_COMMIT();

    int buf = 0;
    for (int t = 0; t < Tn; t++) {
        if (t + 1 < Tn) {
            const int nb = buf ^ 1;
            uint32_t sa = as_base + nb * (SM_BUF * 2) + st_off;
            uint32_t sb = bs_base + nb * (SM_BUF * 2) + st_off;
            const __nv_bfloat16* ga2 = ga + (t + 1) * 32;
            const __nv_bfloat16* gb2 = gb + (t + 1) * 32;
            cp16(sa, ga2); cp16(sa + 16, ga2 + 8);
            cp16(sb, gb2); cp16(sb + 16, gb2 + 8);
            CP_COMMIT();
            CP_WAIT1();
        } else {
            CP_WAIT0();
        }
        __syncthreads();

        const uint32_t abase = a_ld + buf * (SM_BUF * 2);
        const uint32_t bbase = b_ld + buf * (SM_BUF * 2);
#pragma unroll
        for (int ks = 0; ks < 2; ks++) {
            uint32_t af[2][4], bf[4][4];
            ldsm4(af[0], abase + ks * 32);
            ldsm4(af[1], abase + 16 * 80 + ks * 32);
#pragma unroll
            for (int ni = 0; ni < 4; ni++)
                ldsm4(bf[ni], bbase + ni * 16 * 80 + ks * 32);
#pragma unroll
            for (int mi = 0; mi < 2; mi++)
#pragma unroll
                for (int ni = 0; ni < 4; ni++) {
                    mma16816(acc[mi][2 * ni],     af[mi], bf[ni][0], bf[ni][2]);
                    mma16816(acc[mi][2 * ni + 1], af[mi], bf[ni][1], bf[ni][3]);
                }
        }
        __syncthreads();   // compute done before next cp.async overwrites buf
        buf ^= 1;
    }

    // -------------------- Epilogue --------------------
    const int lm = lane >> 2;
    const int lc = (lane & 3) * 2;

#pragma unroll
    for (int mi = 0; mi < 2; mi++) {
#pragma unroll
        for (int nj = 0; nj < 8; nj++) {
            const int row = m0 + wm * 32 + mi * 16 + lm;
            const int col = n0 + wn * 64 + nj * 8 + lc;
            const float* c = acc[mi][nj];
#pragma unroll
            for (int h = 0; h < 2; h++) {
                const int r = row + h * 8;
                float v0 = c[2 * h], v1 = c[2 * h + 1];
                if (EPI == 0) {
                    float2 o; o.x = v0; o.y = v1;
                    *(float2*)(Cf + (size_t)r * ldN + col) = o;
                } else if (EPI == 3) {
                    const float2 rr = *(const float2*)(resid + (size_t)r * ldN + col);
                    float2 o;
                    o.x = v0 + bias[col]     + rr.x;
                    o.y = v1 + bias[col + 1] + rr.y;
                    *(float2*)(Cf + (size_t)r * ldN + col) = o;
                } else {  // EPI == 2: bias + exact GELU -> packed [hi|lo|hi]
                    v0 += bias[col];
                    v1 += bias[col + 1];
                    v0 = 0.5f * v0 * (1.0f + erff(v0 * 0.70710678118654752f));
                    v1 = 0.5f * v1 * (1.0f + erff(v1 * 0.70710678118654752f));
                    __nv_bfloat16 h0, l0, h1, l1;
                    split2(v0, h0, l0); split2(v1, h1, l1);
                    __nv_bfloat162 hh, ll;
                    hh.x = h0; hh.y = h1; ll.x = l0; ll.y = l1;
                    __nv_bfloat16* rb = Cp + (size_t)r * (3 * (size_t)ldN);
                    *(__nv_bfloat162*)(rb + col)            = hh;
                    *(__nv_bfloat162*)(rb + ldN + col)      = ll;
                    *(__nv_bfloat162*)(rb + 2 * ldN + col)  = hh;
                }
            }
        }
    }
}

// ---------------------------------------------------------------------------
// Flash attention (fp32), output written directly as packed bf16 [hi|lo|hi]
// grid (N/64, B*H), 256 threads, 4x4 register tiles, online softmax.
// ---------------------------------------------------------------------------
__global__ __launch_bounds__(256, 2) void attn_kernel(
    const float* __restrict__ qkv, __nv_bfloat16* __restrict__ out3)
{
    __shared__ float QT[64][64];
    __shared__ float KP[64][64];
    __shared__ float Vs[64][64];

    const int tid = threadIdx.x;
    const int tn = tid & 15, tm = tid >> 4;
    const int bh = blockIdx.y;
    const int b = bh / NHEAD, h = bh - b * NHEAD;
    const int q0 = blockIdx.x * 64;

    const float* Qg = qkv + (size_t)b * 1024 * QKV_N + h * 64;
    const float* Kg = Qg + D_DIM;
    const float* Vg = Qg + 2 * D_DIM;

    {
        const int r = tid >> 2;
        const float* src = Qg + (size_t)(q0 + r) * QKV_N;
#pragma unroll
        for (int i = 0; i < 4; i++) {
            const int f = (tid & 3) + i * 4;
            float4 v = *(const float4*)(src + f * 4);
            QT[f * 4 + 0][r] = v.x; QT[f * 4 + 1][r] = v.y;
            QT[f * 4 + 2][r] = v.z; QT[f * 4 + 3][r] = v.w;
        }
    }

    float m_run[4], l_run[4], acc[4][4];
#pragma unroll
    for (int i = 0; i < 4; i++) {
        m_run[i] = -1e30f; l_run[i] = 0.f;
#pragma unroll
        for (int j = 0; j < 4; j++) acc[i][j] = 0.f;
    }

    for (int kt = 0; kt < 16; kt++) {
        __syncthreads();
        {
            const int r = tid >> 2;
            const float* ks  = Kg + (size_t)(kt * 64 + r) * QKV_N;
            const float* vsp = Vg + (size_t)(kt * 64 + r) * QKV_N;
#pragma unroll
            for (int i = 0; i < 4; i++) {
                const int f = (tid & 3) + i * 4;
                float4 kv = *(const float4*)(ks + f * 4);
                KP[f * 4 + 0][r] = kv.x; KP[f * 4 + 1][r] = kv.y;
                KP[f * 4 + 2][r] = kv.z; KP[f * 4 + 3][r] = kv.w;
                float4 vv = *(const float4*)(vsp + f * 4);
                *(float4*)&Vs[r][f * 4] = vv;
            }
        }
        __syncthreads();

        float s[4][4];
#pragma unroll
        for (int i = 0; i < 4; i++)
#pragma unroll
            for (int j = 0; j < 4; j++) s[i][j] = 0.f;
#pragma unroll
        for (int d = 0; d < 64; d++) {
            float qr[4], kr[4];
            *(float4*)qr = *(const float4*)&QT[d][tm * 4];
            *(float4*)kr = *(const float4*)&KP[d][tn * 4];
#pragma unroll
            for (int i = 0; i < 4; i++)
#pragma unroll
                for (int j = 0; j < 4; j++)
                    s[i][j] += qr[i] * kr[j];
        }
#pragma unroll
        for (int i = 0; i < 4; i++)
#pragma unroll
            for (int j = 0; j < 4; j++) s[i][j] *= 0.125f;

        float p[4][4];
#pragma unroll
        for (int i = 0; i < 4; i++) {
            float mt = fmaxf(fmaxf(s[i][0], s[i][1]), fmaxf(s[i][2], s[i][3]));
#pragma unroll
            for (int o = 8; o > 0; o >>= 1)
                mt = fmaxf(mt, __shfl_xor_sync(0xffffffffu, mt, o));
            const float mnew = fmaxf(m_run[i], mt);
            const float corr = exp2f((m_run[i] - mnew) * 1.4426950408889634f);
            float rs = 0.f;
#pragma unroll
            for (int j = 0; j < 4; j++) {
                p[i][j] = exp2f((s[i][j] - mnew) * 1.4426950408889634f);
                rs += p[i][j];
            }
#pragma unroll
            for (int o = 8; o > 0; o >>= 1)
                rs += __shfl_xor_sync(0xffffffffu, rs, o);
            l_run[i] = l_run[i] * corr + rs;
            m_run[i] = mnew;
#pragma unroll
            for (int j = 0; j < 4; j++) acc[i][j] *= corr;
        }

        __syncthreads();
#pragma unroll
        for (int i = 0; i < 4; i++)
            *(float4*)&KP[tm * 4 + i][tn * 4] = *(const float4*)&p[i][0];
        __syncthreads();

#pragma unroll
        for (int j4 = 0; j4 < 16; j4++) {
            float pr[4][4];
#pragma unroll
            for (int i = 0; i < 4; i++)
                *(float4*)&pr[i][0] = *(const float4*)&KP[tm * 4 + i][j4 * 4];
#pragma unroll
            for (int jj = 0; jj < 4; jj++) {
                float vr[4];
                *(float4*)vr = *(const float4*)&Vs[j4 * 4 + jj][tn * 4];
#pragma unroll
                for (int i = 0; i < 4; i++)
#pragma unroll
                    for (int dc = 0; dc < 4; dc++)
                        acc[i][dc] += pr[i][jj] * vr[dc];
            }
        }
    }

    // Packed output: row length 3*768, cols [hi at c, lo at 768+c, hi at 1536+c]
#pragma unroll
    for (int i = 0; i < 4; i++) {
        const float inv = 1.0f / l_run[i];
        const int t = b * 1024 + q0 + tm * 4 + i;
        __nv_bfloat16* orow = out3 + (size_t)t * K3_D;
        const int c = h * 64 + tn * 4;
#pragma unroll
        for (int j = 0; j < 4; j++) {
            __nv_bfloat16 hi, lo;
            split2(acc[i][j] * inv, hi, lo);
            orow[c + j]             = hi;
            orow[c + j + D_DIM]     = lo;
            orow[c + j + 2 * D_DIM] = hi;
        }
    }
}

// ---------------------------------------------------------------------------
// Launch
// ---------------------------------------------------------------------------
extern "C" void kernel_launch(void* const* d_in, const int* in_sizes, int n_in,
                              void* d_out, int out_size)
{
    const float* x      = (const float*)d_in[0];
    const float* qkv_w  = (const float*)d_in[1];
    const float* proj_w = (const float*)d_in[2];
    const float* proj_b = (const float*)d_in[3];
    const float* fc1_w  = (const float*)d_in[4];
    const float* fc1_b  = (const float*)d_in[5];
    const float* fc2_w  = (const float*)d_in[6];
    const float* fc2_b  = (const float*)d_in[7];
    const float* n1g    = (const float*)d_in[8];
    const float* n1b    = (const float*)d_in[9];
    const float* n2g    = (const float*)d_in[10];
    const float* n2b    = (const float*)d_in[11];
    float* out = (float*)d_out;

    void *pa3, *pqkv, *ph3, *pwq, *pwp, *pw1, *pw2;
    cudaGetSymbolAddress(&pa3,  g_a3);
    cudaGetSymbolAddress(&pqkv, g_qkv);
    cudaGetSymbolAddress(&ph3,  g_h3);
    cudaGetSymbolAddress(&pwq,  g_wqkv3);
    cudaGetSymbolAddress(&pwp,  g_wproj3);
    cudaGetSymbolAddress(&pw1,  g_wfc13);
    cudaGetSymbolAddress(&pw2,  g_wfc23);
    __nv_bfloat16* a3   = (__nv_bfloat16*)pa3;
    float*         qkv  = (float*)pqkv;
    __nv_bfloat16* h3   = (__nv_bfloat16*)ph3;
    __nv_bfloat16* wq3  = (__nv_bfloat16*)pwq;
    __nv_bfloat16* wp3  = (__nv_bfloat16*)pwp;
    __nv_bfloat16* w13  = (__nv_bfloat16*)pw1;
    __nv_bfloat16* w23  = (__nv_bfloat16*)pw2;

    // 0) pack weights (hi|hi|lo along K)
    pack_w_kernel<<<(QKV_N * D_DIM + 255) / 256, 256>>>(qkv_w,  wq3, QKV_N * D_DIM,  D_DIM);
    pack_w_kernel<<<(D_DIM * D_DIM + 255) / 256, 256>>>(proj_w, wp3, D_DIM * D_DIM,  D_DIM);
    pack_w_kernel<<<(HID_DIM * D_DIM + 255) / 256, 256>>>(fc1_w, w13, HID_DIM * D_DIM, D_DIM);
    pack_w_kernel<<<(D_DIM * HID_DIM + 255) / 256, 256>>>(fc2_w, w23, D_DIM * HID_DIM, HID_DIM);

    // 1) LN1 + pack (hi|lo|hi)
    ln_pack_kernel<<<T_TOK, 256>>>(x, n1g, n1b, a3);
    // 2) QKV = ln1 @ qkv_w^T  -> fp32 [16384, 2304]
    hgemm_kernel<0><<<dim3(QKV_N / 128, T_TOK / 128), 256>>>(
        a3, wq3, nullptr, nullptr, qkv, nullptr, K3_D, QKV_N);
    // 3) attention -> packed a3
    attn_kernel<<<dim3(1024 / 64, 16 * NHEAD), 256>>>(qkv, a3);
    // 4) x1 = x + attn @ proj_w^T + proj_b -> d_out
    hgemm_kernel<3><<<dim3(D_DIM / 128, T_TOK / 128), 256>>>(
        a3, wp3, proj_b, x, out, nullptr, K3_D, D_DIM);
    // 5) LN2 + pack
    ln_pack_kernel<<<T_TOK, 256>>>(out, n2g, n2b, a3);
    // 6) h3 = pack(gelu(ln2 @ fc1_w^T + fc1_b))
    hgemm_kernel<2><<<dim3(HID_DIM / 128, T_TOK / 128), 256>>>(
        a3, w13, fc1_b, nullptr, nullptr, h3, K3_D, HID_DIM);
    // 7) out = x1 + h @ fc2_w^T + fc2_b (in-place residual)
    hgemm_kernel<3><<<dim3(D_DIM / 128, T_TOK / 128), 256>>>(
        h3, w23, fc2_b, out, out, nullptr, K3_H, D_DIM);
}

// round 7
// speedup vs baseline: 1.7806x; 1.1740x over previous
#include <cuda_runtime.h>
#include <cuda_bf16.h>
#include <math.h>
#include <stdint.h>

// ---------------------------------------------------------------------------
// Problem constants
// ---------------------------------------------------------------------------
#define T_TOK 16384          // B*N tokens
#define D_DIM 768
#define HID_DIM 3072
#define NHEAD 12
#define QKV_N 2304
#define K3_D 2304            // 3*768   (hi|lo|hi packed K)
#define K3_H 9216            // 3*3072
#define BH   192             // B*H

// ---------------------------------------------------------------------------
// Scratch (device globals; allocation-free per harness rules)
// ---------------------------------------------------------------------------
__device__ __align__(256) __nv_bfloat16 g_a3  [(size_t)T_TOK * K3_D];   //  72 MB packed activations
__device__ __align__(256) __nv_bfloat16 g_h3  [(size_t)T_TOK * K3_H];   // 288 MB packed gelu(fc1)
__device__ __align__(256) __nv_bfloat16 g_q3  [(size_t)BH * 1024 * 192]; // 75.5 MB
__device__ __align__(256) __nv_bfloat16 g_k3  [(size_t)BH * 1024 * 192]; // 75.5 MB
__device__ __align__(256) __nv_bfloat16 g_v3  [(size_t)BH * 16 * 64 * 192]; // 75.5 MB
__device__ __align__(256) __nv_bfloat16 g_wqkv3 [(size_t)QKV_N  * K3_D];
__device__ __align__(256) __nv_bfloat16 g_wproj3[(size_t)D_DIM  * K3_D];
__device__ __align__(256) __nv_bfloat16 g_wfc13 [(size_t)HID_DIM* K3_D];
__device__ __align__(256) __nv_bfloat16 g_wfc23 [(size_t)D_DIM  * K3_H];

// ---------------------------------------------------------------------------
// PTX helpers (portable: cp.async / ldmatrix / mma.sync)
// ---------------------------------------------------------------------------
__device__ __forceinline__ uint32_t smem_u32(const void* p) {
    uint32_t a;
    asm("{ .reg .u64 t; cvta.to.shared.u64 t, %1; cvt.u32.u64 %0, t; }" : "=r"(a) : "l"(p));
    return a;
}

__device__ __forceinline__ void cp16(uint32_t saddr, const void* gaddr) {
    asm volatile("cp.async.cg.shared.global [%0], [%1], 16;" :: "r"(saddr), "l"(gaddr));
}
#define CP_COMMIT() asm volatile("cp.async.commit_group;" ::: "memory")
#define CP_WAIT1()  asm volatile("cp.async.wait_group 1;" ::: "memory")
#define CP_WAIT0()  asm volatile("cp.async.wait_group 0;" ::: "memory")

__device__ __forceinline__ void ldsm4(uint32_t* r, uint32_t addr) {
    asm volatile("ldmatrix.sync.aligned.m8n8.x4.shared.b16 {%0,%1,%2,%3}, [%4];"
                 : "=r"(r[0]), "=r"(r[1]), "=r"(r[2]), "=r"(r[3]) : "r"(addr));
}

__device__ __forceinline__ void mma16816(float* c, const uint32_t* a,
                                         uint32_t b0, uint32_t b1) {
    asm volatile(
        "mma.sync.aligned.m16n8k16.row.col.f32.bf16.bf16.f32 "
        "{%0,%1,%2,%3}, {%4,%5,%6,%7}, {%8,%9}, {%0,%1,%2,%3};"
        : "+f"(c[0]), "+f"(c[1]), "+f"(c[2]), "+f"(c[3])
        : "r"(a[0]), "r"(a[1]), "r"(a[2]), "r"(a[3]), "r"(b0), "r"(b1));
}

__device__ __forceinline__ void split2(float x, __nv_bfloat16& hi, __nv_bfloat16& lo) {
    hi = __float2bfloat16(x);
    lo = __float2bfloat16(x - __bfloat162float(hi));
}

// ---------------------------------------------------------------------------
// Weight pack: W[N,K] fp32 -> W3[N,3K] bf16 as [hi | hi | lo]
// ---------------------------------------------------------------------------
__global__ __launch_bounds__(256) void pack_w_kernel(
    const float* __restrict__ W, __nv_bfloat16* __restrict__ W3, int NK, int K)
{
    int idx = blockIdx.x * 256 + threadIdx.x;
    if (idx >= NK) return;
    int n = idx / K, k = idx - n * K;
    __nv_bfloat16 hi, lo;
    split2(W[idx], hi, lo);
    size_t base = (size_t)n * 3 * K + k;
    W3[base] = hi; W3[base + K] = hi; W3[base + 2 * K] = lo;
}

// ---------------------------------------------------------------------------
// Fused LayerNorm + activation pack: out3[t, 3*768] = [hi | lo | hi]
// ---------------------------------------------------------------------------
__global__ __launch_bounds__(256) void ln_pack_kernel(
    const float* __restrict__ x, const float* __restrict__ gam,
    const float* __restrict__ bet, __nv_bfloat16* __restrict__ out3)
{
    const int row = blockIdx.x;
    const int tid = threadIdx.x;
    const float* xr = x + (size_t)row * D_DIM;
    float v0 = xr[tid], v1 = xr[tid + 256], v2 = xr[tid + 512];
    float s = v0 + v1 + v2;
    float q = v0 * v0 + v1 * v1 + v2 * v2;

    __shared__ float sred[8], qred[8];
#pragma unroll
    for (int o = 16; o > 0; o >>= 1) {
        s += __shfl_xor_sync(0xffffffffu, s, o);
        q += __shfl_xor_sync(0xffffffffu, q, o);
    }
    if ((tid & 31) == 0) { sred[tid >> 5] = s; qred[tid >> 5] = q; }
    __syncthreads();
    s = 0.f; q = 0.f;
#pragma unroll
    for (int i = 0; i < 8; i++) { s += sred[i]; q += qred[i]; }
    const float mean = s * (1.0f / 768.0f);
    const float var  = q * (1.0f / 768.0f) - mean * mean;
    const float rstd = rsqrtf(var + 1e-6f);

    __nv_bfloat16* orow = out3 + (size_t)row * K3_D;
#pragma unroll
    for (int e = 0; e < 3; e++) {
        const int c = tid + e * 256;
        const float v = (e == 0 ? v0 : (e == 1 ? v1 : v2));
        const float y = (v - mean) * rstd * gam[c] + bet[c];
        __nv_bfloat16 hi, lo;
        split2(y, hi, lo);
        orow[c] = hi; orow[c + D_DIM] = lo; orow[c + 2 * D_DIM] = hi;
    }
}

// ---------------------------------------------------------------------------
// HMMA GEMM (NT): C[M,Nf] = A3[M,K3] * B3[Nf,K3]^T  (bf16 in, fp32 accum)
// CTA 128x128, BK=32, 8 warps 4(m)x2(n), warp tile 32x64, double-buffered.
// EPI: 1 = qkv split-pack into Q3/K3/V3 attention operands
//      2 = bias + exact GELU -> packed bf16 [hi|lo|hi]
//      3 = bias + residual -> fp32
// ---------------------------------------------------------------------------
#define SM_STRIDE 40              // elements per smem row (80 bytes)
#define SM_BUF    (128 * SM_STRIDE)

template <int EPI>
__global__ __launch_bounds__(256) void hgemm_kernel(
    const __nv_bfloat16* __restrict__ A3, const __nv_bfloat16* __restrict__ B3,
    const float* __restrict__ bias, const float* __restrict__ resid,
    float* __restrict__ Cf, __nv_bfloat16* __restrict__ Cp,
    __nv_bfloat16* __restrict__ Q3o, __nv_bfloat16* __restrict__ K3o,
    __nv_bfloat16* __restrict__ V3o,
    int K3, int ldN)
{
    __shared__ __align__(128) __nv_bfloat16 As[2][SM_BUF];
    __shared__ __align__(128) __nv_bfloat16 Bs[2][SM_BUF];

    const int tid  = threadIdx.x;
    const int wid  = tid >> 5;
    const int lane = tid & 31;
    const int wm   = wid >> 1;
    const int wn   = wid & 1;

    const int m0 = blockIdx.y * 128;
    const int n0 = blockIdx.x * 128;

    const int grow = tid >> 1;
    const int ghalf = tid & 1;
    const __nv_bfloat16* ga = A3 + (size_t)(m0 + grow) * K3 + ghalf * 16;
    const __nv_bfloat16* gb = B3 + (size_t)(n0 + grow) * K3 + ghalf * 16;

    const uint32_t as_base = smem_u32(As);
    const uint32_t bs_base = smem_u32(Bs);
    const uint32_t st_off  = grow * 80 + ghalf * 32;

    const uint32_t lrow = lane & 15;
    const uint32_t lcol = (lane >> 4) * 16;
    const uint32_t a_ld = as_base + (wm * 32 + lrow) * 80 + lcol;
    const uint32_t b_ld = bs_base + (wn * 64 + lrow) * 80 + lcol;

    float acc[2][8][4];
#pragma unroll
    for (int i = 0; i < 2; i++)
#pragma unroll
        for (int j = 0; j < 8; j++)
#pragma unroll
            for (int v = 0; v < 4; v++) acc[i][j][v] = 0.f;

    const int Tn = K3 / 32;

    {
        uint32_t sa = as_base + st_off, sb = bs_base + st_off;
        cp16(sa, ga);      cp16(sa + 16, ga + 8);
        cp16(sb, gb);      cp16(sb + 16, gb + 8);
    }
    CP_COMMIT();

    int buf = 0;
    for (int t = 0; t < Tn; t++) {
        if (t + 1 < Tn) {
            const int nb = buf ^ 1;
            uint32_t sa = as_base + nb * (SM_BUF * 2) + st_off;
            uint32_t sb = bs_base + nb * (SM_BUF * 2) + st_off;
            const __nv_bfloat16* ga2 = ga + (t + 1) * 32;
            const __nv_bfloat16* gb2 = gb + (t + 1) * 32;
            cp16(sa, ga2); cp16(sa + 16, ga2 + 8);
            cp16(sb, gb2); cp16(sb + 16, gb2 + 8);
            CP_COMMIT();
            CP_WAIT1();
        } else {
            CP_WAIT0();
        }
        __syncthreads();

        const uint32_t abase = a_ld + buf * (SM_BUF * 2);
        const uint32_t bbase = b_ld + buf * (SM_BUF * 2);
#pragma unroll
        for (int ks = 0; ks < 2; ks++) {
            uint32_t af[2][4], bfr[4][4];
            ldsm4(af[0], abase + ks * 32);
            ldsm4(af[1], abase + 16 * 80 + ks * 32);
#pragma unroll
            for (int ni = 0; ni < 4; ni++)
                ldsm4(bfr[ni], bbase + ni * 16 * 80 + ks * 32);
#pragma unroll
            for (int mi = 0; mi < 2; mi++)
#pragma unroll
                for (int ni = 0; ni < 4; ni++) {
                    mma16816(acc[mi][2 * ni],     af[mi], bfr[ni][0], bfr[ni][2]);
                    mma16816(acc[mi][2 * ni + 1], af[mi], bfr[ni][1], bfr[ni][3]);
                }
        }
        __syncthreads();
        buf ^= 1;
    }

    // -------------------- Epilogue --------------------
    const int lm = lane >> 2;
    const int lc = (lane & 3) * 2;

#pragma unroll
    for (int mi = 0; mi < 2; mi++) {
#pragma unroll
        for (int nj = 0; nj < 8; nj++) {
            const int row = m0 + wm * 32 + mi * 16 + lm;
            const int col = n0 + wn * 64 + nj * 8 + lc;
            const float* c = acc[mi][nj];
#pragma unroll
            for (int h = 0; h < 2; h++) {
                const int r = row + h * 8;
                float v0 = c[2 * h], v1 = c[2 * h + 1];
                if (EPI == 3) {
                    const float2 rr = *(const float2*)(resid + (size_t)r * ldN + col);
                    float2 o;
                    o.x = v0 + bias[col]     + rr.x;
                    o.y = v1 + bias[col + 1] + rr.y;
                    *(float2*)(Cf + (size_t)r * ldN + col) = o;
                } else if (EPI == 2) {
                    v0 += bias[col];
                    v1 += bias[col + 1];
                    v0 = 0.5f * v0 * (1.0f + erff(v0 * 0.70710678118654752f));
                    v1 = 0.5f * v1 * (1.0f + erff(v1 * 0.70710678118654752f));
                    __nv_bfloat16 h0, l0, h1, l1;
                    split2(v0, h0, l0); split2(v1, h1, l1);
                    __nv_bfloat162 hh, ll;
                    hh.x = h0; hh.y = h1; ll.x = l0; ll.y = l1;
                    __nv_bfloat16* rb = Cp + (size_t)r * (3 * (size_t)ldN);
                    *(__nv_bfloat162*)(rb + col)            = hh;
                    *(__nv_bfloat162*)(rb + ldN + col)      = ll;
                    *(__nv_bfloat162*)(rb + 2 * ldN + col)  = hh;
                } else {  // EPI == 1: split-pack Q/K/V attention operands
                    const int b  = r >> 10, n = r & 1023;
                    const int which = col / 768;
                    const int rem = col - which * 768;
                    const int hh_ = rem >> 6, d = rem & 63;
                    const int bh = b * NHEAD + hh_;
                    __nv_bfloat16 h0, l0, h1, l1;
                    split2(v0, h0, l0); split2(v1, h1, l1);
                    __nv_bfloat162 hp, lp;
                    hp.x = h0; hp.y = h1; lp.x = l0; lp.y = l1;
                    if (which == 0) {          // Q: [hi | lo | hi]
                        __nv_bfloat16* base = Q3o + ((size_t)bh * 1024 + n) * 192;
                        *(__nv_bfloat162*)(base + d)       = hp;
                        *(__nv_bfloat162*)(base + 64 + d)  = lp;
                        *(__nv_bfloat162*)(base + 128 + d) = hp;
                    } else if (which == 1) {   // K: [hi | hi | lo]
                        __nv_bfloat16* base = K3o + ((size_t)bh * 1024 + n) * 192;
                        *(__nv_bfloat162*)(base + d)       = hp;
                        *(__nv_bfloat162*)(base + 64 + d)  = hp;
                        *(__nv_bfloat162*)(base + 128 + d) = lp;
                    } else {                   // V tile [(bh,kt)][64 d][hi|hi|lo over j]
                        const int kt = n >> 6, j = n & 63;
                        __nv_bfloat16* tb = V3o + ((size_t)(bh * 16 + kt) * 64) * 192;
                        __nv_bfloat16* r0p = tb + (size_t)d * 192;
                        __nv_bfloat16* r1p = r0p + 192;
                        r0p[j] = h0; r0p[64 + j] = h0; r0p[128 + j] = l0;
                        r1p[j] = h1; r1p[64 + j] = h1; r1p[128 + j] = l1;
                    }
                }
            }
        }
    }
}

// ---------------------------------------------------------------------------
// Tensor-core flash attention. grid (16 qtiles, 192 bh), 128 threads / 4 warps.
// S = Q3[64x192] * K3[64x192]^T per key tile (16 tiles), online softmax on
// fragments, P split-packed to smem, O += P3[64x192] * V3tile[64x192]^T.
// Output written packed [hi|lo|hi] into a3 for the proj GEMM.
// ---------------------------------------------------------------------------
#define ATT_STRIDE 200       // elems per smem row (400 B, ldmatrix conflict-free)
#define ATT_TILE   (64 * ATT_STRIDE)
#define ATT_SMEM   (4 * ATT_TILE * 2)

__global__ __launch_bounds__(128) void fattn_kernel(
    const __nv_bfloat16* __restrict__ q3, const __nv_bfloat16* __restrict__ k3,
    const __nv_bfloat16* __restrict__ v3, __nv_bfloat16* __restrict__ out3)
{
    extern __shared__ __nv_bfloat16 sm[];
    __nv_bfloat16* Qs = sm;
    __nv_bfloat16* Ks = Qs + ATT_TILE;
    __nv_bfloat16* Vs = Ks + ATT_TILE;
    __nv_bfloat16* Ps = Vs + ATT_TILE;

    const int tid = threadIdx.x, wid = tid >> 5, lane = tid & 31;
    const int qt = blockIdx.x, bh = blockIdx.y;
    const int q0 = qt * 64;

    const uint32_t qs_u = smem_u32(Qs);
    const uint32_t ks_u = smem_u32(Ks);
    const uint32_t vs_u = smem_u32(Vs);

    // Load Q tile once (64 rows x 192 elems)
    {
        const __nv_bfloat16* gQ = q3 + ((size_t)bh * 1024 + q0) * 192;
#pragma unroll
        for (int i = 0; i < 12; i++) {
            const int e = tid + i * 128;
            const int rw = e / 24, cc = e % 24;
            cp16(qs_u + rw * 400 + cc * 16, gQ + rw * 192 + cc * 8);
        }
    }
    CP_COMMIT();

    const uint32_t lrow = lane & 15;
    const uint32_t lcolb = (lane >> 4) * 16;
    const uint32_t a_q = qs_u + (wid * 16 + lrow) * 400 + lcolb;
    const uint32_t a_p = smem_u32(Ps) + (wid * 16 + lrow) * 400 + lcolb;

    float mrun[2] = {-1e30f, -1e30f}, lrun[2] = {0.f, 0.f};
    float accO[8][4];
#pragma unroll
    for (int f = 0; f < 8; f++)
#pragma unroll
        for (int v = 0; v < 4; v++) accO[f][v] = 0.f;

    for (int kt = 0; kt < 16; kt++) {
        __syncthreads();   // prior iteration's PV reads of Ks/Vs/Ps done
        {
            const __nv_bfloat16* gK = k3 + ((size_t)bh * 1024 + kt * 64) * 192;
            const __nv_bfloat16* gV = v3 + ((size_t)(bh * 16 + kt) * 64) * 192;
#pragma unroll
            for (int i = 0; i < 12; i++) {
                const int e = tid + i * 128;
                const int rw = e / 24, cc = e % 24;
                cp16(ks_u + rw * 400 + cc * 16, gK + rw * 192 + cc * 8);
                cp16(vs_u + rw * 400 + cc * 16, gV + rw * 192 + cc * 8);
            }
        }
        CP_COMMIT();
        CP_WAIT0();
        __syncthreads();

        // ---- S = Q * K^T (k=192, 12 k16 steps) ----
        float sacc[8][4];
#pragma unroll
        for (int f = 0; f < 8; f++)
#pragma unroll
            for (int v = 0; v < 4; v++) sacc[f][v] = 0.f;
#pragma unroll
        for (int ks = 0; ks < 12; ks++) {
            uint32_t af[4], bfr[4][4];
            ldsm4(af, a_q + ks * 32);
#pragma unroll
            for (int ni = 0; ni < 4; ni++)
                ldsm4(bfr[ni], ks_u + (ni * 16 + lrow) * 400 + lcolb + ks * 32);
#pragma unroll
            for (int ni = 0; ni < 4; ni++) {
                mma16816(sacc[2 * ni],     af, bfr[ni][0], bfr[ni][2]);
                mma16816(sacc[2 * ni + 1], af, bfr[ni][1], bfr[ni][3]);
            }
        }
#pragma unroll
        for (int f = 0; f < 8; f++)
#pragma unroll
            for (int v = 0; v < 4; v++) sacc[f][v] *= 0.125f;

        // ---- online softmax (2 rows per thread: lane>>2 and +8) ----
#pragma unroll
        for (int hf = 0; hf < 2; hf++) {
            float mt = -1e30f;
#pragma unroll
            for (int f = 0; f < 8; f++)
                mt = fmaxf(mt, fmaxf(sacc[f][2 * hf], sacc[f][2 * hf + 1]));
            mt = fmaxf(mt, __shfl_xor_sync(0xffffffffu, mt, 1));
            mt = fmaxf(mt, __shfl_xor_sync(0xffffffffu, mt, 2));
            const float mnew = fmaxf(mrun[hf], mt);
            const float corr = exp2f((mrun[hf] - mnew) * 1.4426950408889634f);
            float rs = 0.f;
            const int prow = wid * 16 + (lane >> 2) + hf * 8;
            __nv_bfloat16* pb = Ps + prow * ATT_STRIDE + (lane & 3) * 2;
#pragma unroll
            for (int f = 0; f < 8; f++) {
                float p0 = exp2f((sacc[f][2 * hf]     - mnew) * 1.4426950408889634f);
                float p1 = exp2f((sacc[f][2 * hf + 1] - mnew) * 1.4426950408889634f);
                rs += p0 + p1;
                __nv_bfloat16 h0, l0, h1, l1;
                split2(p0, h0, l0); split2(p1, h1, l1);
                __nv_bfloat162 hp, lp;
                hp.x = h0; hp.y = h1; lp.x = l0; lp.y = l1;
                *(__nv_bfloat162*)(pb + f * 8)        = hp;   // Phi
                *(__nv_bfloat162*)(pb + 64 + f * 8)   = lp;   // Plo
                *(__nv_bfloat162*)(pb + 128 + f * 8)  = hp;   // Phi
            }
            rs += __shfl_xor_sync(0xffffffffu, rs, 1);
            rs += __shfl_xor_sync(0xffffffffu, rs, 2);
            lrun[hf] = lrun[hf] * corr + rs;
            mrun[hf] = mnew;
#pragma unroll
            for (int f = 0; f < 8; f++) {
                accO[f][2 * hf]     *= corr;
                accO[f][2 * hf + 1] *= corr;
            }
        }
        __syncthreads();   // P visible to all warps (each warp reads only own rows,
                           // but keep full sync for Vs lifetime symmetry)

        // ---- O += P * V^T-tile (k=192) ----
#pragma unroll
        for (int ks = 0; ks < 12; ks++) {
            uint32_t af[4], bfr[4][4];
            ldsm4(af, a_p + ks * 32);
#pragma unroll
            for (int ni = 0; ni < 4; ni++)
                ldsm4(bfr[ni], vs_u + (ni * 16 + lrow) * 400 + lcolb + ks * 32);
#pragma unroll
            for (int ni = 0; ni < 4; ni++) {
                mma16816(accO[2 * ni],     af, bfr[ni][0], bfr[ni][2]);
                mma16816(accO[2 * ni + 1], af, bfr[ni][1], bfr[ni][3]);
            }
        }
    }

    // ---- normalize + pack [hi|lo|hi] into a3 ----
    const int b = bh / NHEAD, h = bh - b * NHEAD;
#pragma unroll
    for (int hf = 0; hf < 2; hf++) {
        const float inv = 1.0f / lrun[hf];
        const int t = b * 1024 + q0 + wid * 16 + (lane >> 2) + hf * 8;
        __nv_bfloat16* orow = out3 + (size_t)t * K3_D;
        const int cbase = h * 64 + (lane & 3) * 2;
#pragma unroll
        for (int f = 0; f < 8; f++) {
            const float v0 = accO[f][2 * hf] * inv;
            const float v1 = accO[f][2 * hf + 1] * inv;
            __nv_bfloat16 h0, l0, h1, l1;
            split2(v0, h0, l0); split2(v1, h1, l1);
            __nv_bfloat162 hp, lp;
            hp.x = h0; hp.y = h1; lp.x = l0; lp.y = l1;
            const int c = cbase + f * 8;
            *(__nv_bfloat162*)(orow + c)             = hp;
            *(__nv_bfloat162*)(orow + c + D_DIM)     = lp;
            *(__nv_bfloat162*)(orow + c + 2 * D_DIM) = hp;
        }
    }
}

// ---------------------------------------------------------------------------
// Launch
// ---------------------------------------------------------------------------
extern "C" void kernel_launch(void* const* d_in, const int* in_sizes, int n_in,
                              void* d_out, int out_size)
{
    const float* x      = (const float*)d_in[0];
    const float* qkv_w  = (const float*)d_in[1];
    const float* proj_w = (const float*)d_in[2];
    const float* proj_b = (const float*)d_in[3];
    const float* fc1_w  = (const float*)d_in[4];
    const float* fc1_b  = (const float*)d_in[5];
    const float* fc2_w  = (const float*)d_in[6];
    const float* fc2_b  = (const float*)d_in[7];
    const float* n1g    = (const float*)d_in[8];
    const float* n1b    = (const float*)d_in[9];
    const float* n2g    = (const float*)d_in[10];
    const float* n2b    = (const float*)d_in[11];
    float* out = (float*)d_out;

    void *pa3, *ph3, *pq3, *pk3, *pv3, *pwq, *pwp, *pw1, *pw2;
    cudaGetSymbolAddress(&pa3, g_a3);
    cudaGetSymbolAddress(&ph3, g_h3);
    cudaGetSymbolAddress(&pq3, g_q3);
    cudaGetSymbolAddress(&pk3, g_k3);
    cudaGetSymbolAddress(&pv3, g_v3);
    cudaGetSymbolAddress(&pwq, g_wqkv3);
    cudaGetSymbolAddress(&pwp, g_wproj3);
    cudaGetSymbolAddress(&pw1, g_wfc13);
    cudaGetSymbolAddress(&pw2, g_wfc23);
    __nv_bfloat16* a3  = (__nv_bfloat16*)pa3;
    __nv_bfloat16* h3  = (__nv_bfloat16*)ph3;
    __nv_bfloat16* q3  = (__nv_bfloat16*)pq3;
    __nv_bfloat16* k3  = (__nv_bfloat16*)pk3;
    __nv_bfloat16* v3  = (__nv_bfloat16*)pv3;
    __nv_bfloat16* wq3 = (__nv_bfloat16*)pwq;
    __nv_bfloat16* wp3 = (__nv_bfloat16*)pwp;
    __nv_bfloat16* w13 = (__nv_bfloat16*)pw1;
    __nv_bfloat16* w23 = (__nv_bfloat16*)pw2;

    cudaFuncSetAttribute(fattn_kernel, cudaFuncAttributeMaxDynamicSharedMemorySize, ATT_SMEM);

    // 0) pack weights (hi|hi|lo along K)
    pack_w_kernel<<<(QKV_N * D_DIM + 255) / 256, 256>>>(qkv_w,  wq3, QKV_N * D_DIM,  D_DIM);
    pack_w_kernel<<<(D_DIM * D_DIM + 255) / 256, 256>>>(proj_w, wp3, D_DIM * D_DIM,  D_DIM);
    pack_w_kernel<<<(HID_DIM * D_DIM + 255) / 256, 256>>>(fc1_w, w13, HID_DIM * D_DIM, D_DIM);
    pack_w_kernel<<<(D_DIM * HID_DIM + 255) / 256, 256>>>(fc2_w, w23, D_DIM * HID_DIM, HID_DIM);

    // 1) LN1 + pack (hi|lo|hi)
    ln_pack_kernel<<<T_TOK, 256>>>(x, n1g, n1b, a3);
    // 2) QKV GEMM -> split-packed Q3/K3/V3 attention operands
    hgemm_kernel<1><<<dim3(QKV_N / 128, T_TOK / 128), 256>>>(
        a3, wq3, nullptr, nullptr, nullptr, nullptr, q3, k3, v3, K3_D, QKV_N);
    // 3) tensor-core flash attention -> packed a3
    fattn_kernel<<<dim3(16, BH), 128, ATT_SMEM>>>(q3, k3, v3, a3);
    // 4) x1 = x + attn @ proj_w^T + proj_b -> d_out
    hgemm_kernel<3><<<dim3(D_DIM / 128, T_TOK / 128), 256>>>(
        a3, wp3, proj_b, x, out, nullptr, nullptr, nullptr, nullptr, K3_D, D_DIM);
    // 5) LN2 + pack
    ln_pack_kernel<<<T_TOK, 256>>>(out, n2g, n2b, a3);
    // 6) h3 = pack(gelu(ln2 @ fc1_w^T + fc1_b))
    hgemm_kernel<2><<<dim3(HID_DIM / 128, T_TOK / 128), 256>>>(
        a3, w13, fc1_b, nullptr, nullptr, h3, nullptr, nullptr, nullptr, K3_D, HID_DIM);
    // 7) out = x1 + h @ fc2_w^T + fc2_b (in-place residual)
    hgemm_kernel<3><<<dim3(D_DIM / 128, T_TOK / 128), 256>>>(
        h3, w23, fc2_b, out, out, nullptr, nullptr, nullptr, nullptr, K3_H, D_DIM);
}